// round 10
// baseline (speedup 1.0000x reference)
#include <cuda_runtime.h>
#include <cstdint>
#include <math.h>

#define D        256
#define MC       1024
#define NTOK     65536
#define BM       128
#define BN       256
#define KC       32
#define LDP      36                       // padded row stride (floats)
#define LDPB     (LDP * 4)                // 144 bytes
#define A_BYTES  (BM * LDP * 4)           // 18432
#define B_BYTES  (BN * LDP * 4)           // 36864
#define STAGE_BYTES (A_BYTES + B_BYTES)   // 55296
#define OFF_SNE   0
#define OFF_RED   4096                    // 4 arrays [32][128] = 64KB
#define OFF_STAGE 69632
#define SMEM_TOTAL (OFF_STAGE + 2 * STAGE_BYTES)   // 180224
#define NCHUNKS  32                       // 4 nt * 8 kc
#define NCAND    8
#define FINF     3.4e38f
#define IMAX     0x7fffffff
#define ELD      260                      // candidate-row smem stride (floats)

// ---- scratch (static, no allocations) ----
__device__ float g_xh[NTOK * D];          // tf32-rounded x
__device__ float g_eh[MC * D];            // tf32-rounded e
__device__ float g_normX[NTOK];
__device__ float g_normE[MC];
__device__ int   g_cand[NTOK * NCAND];
__device__ float g_counts[MC];
__device__ float g_sumsq;

static __device__ __forceinline__ uint32_t s2u(const void* p) {
    uint32_t a;
    asm("{ .reg .u64 t; cvta.to.shared.u64 t, %1; cvt.u32.u64 %0, t; }" : "=r"(a) : "l"(p));
    return a;
}
static __device__ __forceinline__ float tf32r(float a) {
    uint32_t r;
    asm("cvt.rna.tf32.f32 %0, %1;" : "=r"(r) : "f"(a));
    return __uint_as_float(r);
}
static __device__ __forceinline__ float fmarn(float a, float b, float c) {
    float d;
    asm("fma.rn.f32 %0, %1, %2, %3;" : "=f"(d) : "f"(a), "f"(b), "f"(c));
    return d;
}
#define CP_ASYNC16(dst, src) \
    asm volatile("cp.async.cg.shared.global [%0], [%1], 16;" :: "r"(dst), "l"(src))
#define CP_COMMIT()  asm volatile("cp.async.commit_group;" ::: "memory")
#define CP_WAIT(n)   asm volatile("cp.async.wait_group %0;" :: "n"(n) : "memory")

#define LDSM_X4(r0, r1, r2, r3, addr) \
    asm volatile("ldmatrix.sync.aligned.m8n8.x4.shared.b16 {%0,%1,%2,%3}, [%4];" \
        : "=r"(r0), "=r"(r1), "=r"(r2), "=r"(r3) : "r"(addr))

static __device__ __forceinline__ void mma_tf32(float& c0, float& c1, float& c2, float& c3,
                                                uint32_t a0, uint32_t a1, uint32_t a2, uint32_t a3,
                                                uint32_t b0, uint32_t b1) {
    asm volatile(
        "mma.sync.aligned.m16n8k8.row.col.f32.tf32.tf32.f32 "
        "{%0,%1,%2,%3}, {%4,%5,%6,%7}, {%8,%9}, {%0,%1,%2,%3};"
        : "+f"(c0), "+f"(c1), "+f"(c2), "+f"(c3)
        : "r"(a0), "r"(a1), "r"(a2), "r"(a3), "r"(b0), "r"(b1));
}

// ---------------- init ----------------
__global__ void init_kernel() {
    int t = threadIdx.x;
    if (t < MC) g_counts[t] = 0.0f;
    if (t == 0) g_sumsq = 0.0f;
}

// ---------------- tf32 round + exact row norms (bitwise-R1 norm arithmetic) ----------------
__global__ void split_kernel(const float* __restrict__ src, int which) {
    int warp = threadIdx.x >> 5, lane = threadIdx.x & 31;
    int row = blockIdx.x * 8 + warp;
    float* hi = which ? g_eh : g_xh;
    const float4* r4 = (const float4*)(src + ((size_t)row << 8));
    float4* h4 = (float4*)(hi + ((size_t)row << 8));
    float s = 0.0f;
#pragma unroll
    for (int j = 0; j < 2; ++j) {
        float4 v = r4[lane + 32 * j];
        float4 h;
        h.x = tf32r(v.x); h.y = tf32r(v.y); h.z = tf32r(v.z); h.w = tf32r(v.w);
        h4[lane + 32 * j] = h;
        s += v.x * v.x + v.y * v.y + v.z * v.z + v.w * v.w;
    }
#pragma unroll
    for (int o = 16; o > 0; o >>= 1) s += __shfl_xor_sync(0xffffffffu, s, o);
    if (lane == 0) {
        if (which) g_normE[row] = s; else g_normX[row] = s;
    }
}

// ---------------- 16-warp TF32 GEMM (ldmatrix fragments) + smem best-2 sketch ----------------
// warp grid 2(M) x 8(N); warp tile 64x32; per-thread acc 4x4x4
__global__ __launch_bounds__(512, 1)
void mma_argmin_kernel() {
    extern __shared__ char smem[];
    uint32_t sb = s2u(smem);
    float* sne = (float*)(smem + OFF_SNE);
    float* sV1 = (float*)(smem + OFF_RED);          // [32][128]
    float* sV2 = sV1 + 4096;
    int*   sI1 = (int*)(sV2 + 4096);
    int*   sI2 = sI1 + 4096;

    int tid = threadIdx.x, wid = tid >> 5, lane = tid & 31;
    int warp_m = wid & 1, warp_n = wid >> 1;        // 2 x 8
    int lg = lane >> 2, lt = lane & 3;
    int row0 = blockIdx.x * BM;
    int slot = warp_n * 4 + lt;                     // 32 slots

    for (int i = tid; i < MC; i += 512) sne[i] = g_normE[i];
    for (int i = tid; i < 4096; i += 512) {
        sV1[i] = FINF; sV2[i] = FINF; sI1[i] = IMAX; sI2[i] = IMAX;
    }

    float nx8[8];
#pragma unroll
    for (int mt = 0; mt < 4; ++mt)
#pragma unroll
        for (int i = 0; i < 2; ++i)
            nx8[mt * 2 + i] = g_normX[row0 + warp_m * 64 + mt * 16 + i * 8 + lg];

    float acc[4][4][4];
#pragma unroll
    for (int mt = 0; mt < 4; ++mt)
#pragma unroll
        for (int n8 = 0; n8 < 4; ++n8)
#pragma unroll
            for (int q = 0; q < 4; ++q) acc[mt][n8][q] = 0.0f;

    // ldmatrix per-lane base offsets (computed once)
    int grp = lane >> 3, lr = lane & 7;
    uint32_t aOff[4];
#pragma unroll
    for (int mt = 0; mt < 4; ++mt)
        aOff[mt] = (uint32_t)((warp_m * 64 + mt * 16 + lr + (grp & 1) * 8) * LDPB)
                 + (uint32_t)((grp >> 1) * 16);
    uint32_t bOff = (uint32_t)A_BYTES
                  + (uint32_t)((warp_n * 32 + grp * 8 + lr) * LDPB);

    // cp.async loaders: A = 1024 16B-segs (2/thread), B = 2048 (4/thread)
    int a_r = tid >> 2, a_s = (tid & 3) * 2;        // A row, first seg
    int b_r = tid >> 1, b_s = (tid & 1) * 4;        // B row, first seg
    auto load_chunk = [&](int c) {
        int nt = c >> 3, kc = c & 7;
        int kbase = kc * KC;
        uint32_t stage = sb + OFF_STAGE + (c & 1) * STAGE_BYTES;
        const float* asrc = g_xh + ((size_t)(row0 + a_r) << 8) + kbase + a_s * 4;
        uint32_t adst = stage + a_r * LDPB + a_s * 16;
        CP_ASYNC16(adst,      asrc);
        CP_ASYNC16(adst + 16, asrc + 4);
        const float* bsrc = g_eh + ((size_t)(nt * BN + b_r) << 8) + kbase + b_s * 4;
        uint32_t bdst = stage + A_BYTES + b_r * LDPB + b_s * 16;
#pragma unroll
        for (int j = 0; j < 4; ++j) CP_ASYNC16(bdst + j * 16, bsrc + j * 4);
    };

    __syncthreads();   // sne/red ready
    load_chunk(0); CP_COMMIT();

    for (int c = 0; c < NCHUNKS; ++c) {
        if (c + 1 < NCHUNKS) { load_chunk(c + 1); CP_COMMIT(); CP_WAIT(1); }
        else CP_WAIT(0);
        __syncthreads();

        uint32_t stageAddr = sb + OFF_STAGE + (c & 1) * STAGE_BYTES;

#pragma unroll
        for (int ks = 0; ks < 4; ++ks) {
            uint32_t kb = ks * 32;
            uint32_t a[4][4], b0[4], b1[4];
#pragma unroll
            for (int mt = 0; mt < 4; ++mt)
                LDSM_X4(a[mt][0], a[mt][1], a[mt][2], a[mt][3],
                        stageAddr + aOff[mt] + kb);
            LDSM_X4(b0[0], b0[1], b0[2], b0[3], stageAddr + bOff + kb);
            LDSM_X4(b1[0], b1[1], b1[2], b1[3], stageAddr + bOff + kb + 16);
#pragma unroll
            for (int mt = 0; mt < 4; ++mt)
#pragma unroll
                for (int n8 = 0; n8 < 4; ++n8)
                    mma_tf32(acc[mt][n8][0], acc[mt][n8][1], acc[mt][n8][2], acc[mt][n8][3],
                             a[mt][0], a[mt][1], a[mt][2], a[mt][3], b0[n8], b1[n8]);
        }

        if ((c & 7) == 7) {
            int nt = c >> 3;
#pragma unroll
            for (int mt = 0; mt < 4; ++mt)
#pragma unroll
                for (int i = 0; i < 2; ++i) {
                    int rl = warp_m * 64 + mt * 16 + i * 8 + lg;
                    float nx = nx8[mt * 2 + i];
                    float tv1 = FINF, tv2 = FINF; int ti1 = IMAX, ti2 = IMAX;
#pragma unroll
                    for (int n8 = 0; n8 < 4; ++n8) {
                        int cbase = nt * BN + warp_n * 32 + n8 * 8 + 2 * lt;
#pragma unroll
                        for (int q = 0; q < 2; ++q) {
                            float dot = acc[mt][n8][i * 2 + q];
                            float d = (sne[cbase + q] + nx) - 2.0f * dot;
                            int cc = cbase + q;
                            if (d < tv1 || (d == tv1 && cc < ti1)) {
                                tv2 = tv1; ti2 = ti1; tv1 = d; ti1 = cc;
                            } else if (d < tv2 || (d == tv2 && cc < ti2)) {
                                tv2 = d; ti2 = cc;
                            }
                        }
                    }
                    int o = slot * 128 + rl;
                    float mv1 = sV1[o], mv2 = sV2[o]; int mi1 = sI1[o], mi2 = sI2[o];
                    if (tv1 < mv1 || (tv1 == mv1 && ti1 < mi1)) {
                        mv2 = mv1; mi2 = mi1; mv1 = tv1; mi1 = ti1;
                    } else if (tv1 < mv2 || (tv1 == mv2 && ti1 < mi2)) {
                        mv2 = tv1; mi2 = ti1;
                    }
                    if (tv2 < mv1 || (tv2 == mv1 && ti2 < mi1)) {
                        mv2 = mv1; mi2 = mi1; mv1 = tv2; mi1 = ti2;
                    } else if (tv2 < mv2 || (tv2 == mv2 && ti2 < mi2)) {
                        mv2 = tv2; mi2 = ti2;
                    }
                    sV1[o] = mv1; sV2[o] = mv2; sI1[o] = mi1; sI2[o] = mi2;
                }
#pragma unroll
            for (int mt = 0; mt < 4; ++mt)
#pragma unroll
                for (int n8 = 0; n8 < 4; ++n8)
#pragma unroll
                    for (int q = 0; q < 4; ++q) acc[mt][n8][q] = 0.0f;
        }
        __syncthreads();   // all reads of stage (c&1) done before overwrite
    }

    // per-row top-8 of 32 slots x best-2 = 64 candidates
    if (tid < BM) {
        unsigned usedA = 0, usedB = 0;
#pragma unroll 1
        for (int sel = 0; sel < NCAND; ++sel) {
            float bv = FINF; int bi = IMAX; int bs = 0; int barr = 0;
            for (int s = 0; s < 32; ++s) {
                float v1 = sV1[s * 128 + tid]; int i1 = sI1[s * 128 + tid];
                float v2 = sV2[s * 128 + tid]; int i2 = sI2[s * 128 + tid];
                bool okA = !((usedA >> s) & 1u), okB = !((usedB >> s) & 1u);
                if (okA && (v1 < bv || (v1 == bv && i1 < bi))) { bv = v1; bi = i1; bs = s; barr = 0; }
                if (okB && (v2 < bv || (v2 == bv && i2 < bi))) { bv = v2; bi = i2; bs = s; barr = 1; }
            }
            if (barr) usedB |= 1u << bs; else usedA |= 1u << bs;
            g_cand[(size_t)(row0 + tid) * NCAND + sel] = bi;
        }
    }
}

// ---------------- fused refine (SERIAL-chain exact fp32) + gather + loss + histogram ----------------
__global__ __launch_bounds__(128, 8)
void refine_gather_kernel(const float* __restrict__ x, const float* __restrict__ emb,
                          float* __restrict__ d_out, long long idx_off, int write_idx) {
    __shared__ float sx[4][D];            // x rows
    __shared__ float se[4][NCAND * ELD];  // candidate rows, stride ELD
    int warp = threadIdx.x >> 5, lane = threadIdx.x & 31;
    int row = blockIdx.x * 4 + warp;

    int ci = 0;
    if (lane < NCAND) ci = g_cand[(size_t)row * NCAND + lane];
    int cj[NCAND];
#pragma unroll
    for (int j = 0; j < NCAND; ++j) cj[j] = __shfl_sync(0xffffffffu, ci, j);

    const float4* x4 = (const float4*)(x + ((size_t)row << 8));
    float4 xv0 = x4[lane], xv1 = x4[lane + 32];
    *(float4*)&sx[warp][lane * 4]        = xv0;
    *(float4*)&sx[warp][128 + lane * 4]  = xv1;

#pragma unroll
    for (int j = 0; j < NCAND; ++j) {
        const float4* e4 = (const float4*)(emb + ((size_t)cj[j] << 8));
        *(float4*)&se[warp][j * ELD + lane * 4]       = __ldg(&e4[lane]);
        *(float4*)&se[warp][j * ELD + 128 + lane * 4] = __ldg(&e4[lane + 32]);
    }
    __syncwarp();

    float myd = FINF;
    if (lane < NCAND) {
        const float* xs = sx[warp];
        const float* es = &se[warp][lane * ELD];
        float dot = 0.0f;
#pragma unroll 8
        for (int k4 = 0; k4 < 64; ++k4) {
            float4 xv = *(const float4*)&xs[k4 * 4];
            float4 ev = *(const float4*)&es[k4 * 4];
            dot = fmarn(xv.x, ev.x, dot);
            dot = fmarn(xv.y, ev.y, dot);
            dot = fmarn(xv.z, ev.z, dot);
            dot = fmarn(xv.w, ev.w, dot);
        }
        myd = (g_normX[row] + g_normE[cj[lane]]) - 2.0f * dot;
    }
    float dv[NCAND];
#pragma unroll
    for (int j = 0; j < NCAND; ++j) dv[j] = __shfl_sync(0xffffffffu, myd, j);
    float bv = FINF; int bi = IMAX; int bj = 0;
#pragma unroll
    for (int j = 0; j < NCAND; ++j) {
        if (dv[j] < bv || (dv[j] == bv && cj[j] < bi)) { bv = dv[j]; bi = cj[j]; bj = j; }
    }
    if (lane == 0 && write_idx) d_out[idx_off + row] = (float)bi;

    const float* qs = &se[warp][bj * ELD];
    float4* o4 = (float4*)(d_out + ((size_t)row << 8));
    float s = 0.0f;
    {
        float4 q = *(const float4*)&qs[lane * 4];
        float4 o;
        o.x = xv0.x + (q.x - xv0.x); o.y = xv0.y + (q.y - xv0.y);
        o.z = xv0.z + (q.z - xv0.z); o.w = xv0.w + (q.w - xv0.w);
        o4[lane] = o;
        float dx = xv0.x - q.x, dy = xv0.y - q.y, dz = xv0.z - q.z, dw = xv0.w - q.w;
        s += dx * dx + dy * dy + dz * dz + dw * dw;
    }
    {
        float4 q = *(const float4*)&qs[128 + lane * 4];
        float4 o;
        o.x = xv1.x + (q.x - xv1.x); o.y = xv1.y + (q.y - xv1.y);
        o.z = xv1.z + (q.z - xv1.z); o.w = xv1.w + (q.w - xv1.w);
        o4[lane + 32] = o;
        float dx = xv1.x - q.x, dy = xv1.y - q.y, dz = xv1.z - q.z, dw = xv1.w - q.w;
        s += dx * dx + dy * dy + dz * dz + dw * dw;
    }
#pragma unroll
    for (int o = 16; o > 0; o >>= 1) s += __shfl_xor_sync(0xffffffffu, s, o);
    if (lane == 0) {
        atomicAdd(&g_sumsq, s);
        atomicAdd(&g_counts[bi], 1.0f);
    }
}

// ---------------- loss + perplexity ----------------
__global__ void finalize_kernel(float* __restrict__ d_out, long long loss_off,
                                long long perp_off) {
    __shared__ float red[1024];
    int t = threadIdx.x;
    float p = g_counts[t] * (1.0f / (float)NTOK);
    red[t] = p * logf(p + 1e-10f);
    __syncthreads();
    for (int s = 512; s > 0; s >>= 1) {
        if (t < s) red[t] += red[t + s];
        __syncthreads();
    }
    if (t == 0) {
        d_out[loss_off] = 0.25f * g_sumsq / ((float)NTOK * (float)D);
        d_out[perp_off] = expf(-red[0]);
    }
}

// ---------------- launch ----------------
extern "C" void kernel_launch(void* const* d_in, const int* in_sizes, int n_in,
                              void* d_out, int out_size) {
    const float* x   = (const float*)d_in[0];
    const float* emb = (const float*)d_in[1];
    float* out = (float*)d_out;

    int NT = in_sizes[0] / D;
    long long qn = (long long)in_sizes[0];
    long long loss_off = qn;
    long long idx_off  = qn + 1;
    long long perp_off = qn + 1 + NT;
    int full = (out_size >= (int)(qn + NT + 2)) ? 1 : 0;

    cudaFuncSetAttribute(mma_argmin_kernel, cudaFuncAttributeMaxDynamicSharedMemorySize,
                         SMEM_TOTAL);

    init_kernel<<<1, 1024>>>();
    split_kernel<<<NT / 8, 256>>>(x, 0);
    split_kernel<<<MC / 8, 256>>>(emb, 1);
    mma_argmin_kernel<<<NT / BM, 512, SMEM_TOTAL>>>();
    refine_gather_kernel<<<NT / 4, 128>>>(x, emb, out, idx_off, full);
    if (full) finalize_kernel<<<1, 1024>>>(out, loss_off, perp_off);
}

// round 11
// speedup vs baseline: 1.1125x; 1.1125x over previous
#include <cuda_runtime.h>
#include <cstdint>
#include <math.h>

#define D        256
#define MC       1024
#define NTOK     65536
#define BM       128
#define BN       256
#define KC       32
#define LDP      36                       // padded row stride (floats)
#define LDPB     (LDP * 4)                // 144 bytes
#define A_BYTES  (BM * LDP * 4)           // 18432
#define B_BYTES  (BN * LDP * 4)           // 36864
#define STAGE_BYTES (A_BYTES + B_BYTES)   // 55296
#define OFF_SNE   0
#define OFF_RED   4096                    // 4 arrays [32][128] = 64KB
#define OFF_STAGE 69632
#define SMEM_TOTAL (OFF_STAGE + 2 * STAGE_BYTES)   // 180224
#define NCHUNKS  32                       // 4 nt * 8 kc
#define NCAND    4
#define FINF     3.4e38f
#define IMAX     0x7fffffff
#define ELD      260                      // candidate-row smem stride (floats)

// ---- scratch (static, no allocations) ----
__device__ float g_normX[NTOK];
__device__ float g_normE[MC];
__device__ int   g_cand[NTOK * NCAND];
__device__ float g_counts[MC];
__device__ float g_sumsq;

static __device__ __forceinline__ uint32_t s2u(const void* p) {
    uint32_t a;
    asm("{ .reg .u64 t; cvta.to.shared.u64 t, %1; cvt.u32.u64 %0, t; }" : "=r"(a) : "l"(p));
    return a;
}
static __device__ __forceinline__ float fmarn(float a, float b, float c) {
    float d;
    asm("fma.rn.f32 %0, %1, %2, %3;" : "=f"(d) : "f"(a), "f"(b), "f"(c));
    return d;
}
#define CP_ASYNC16(dst, src) \
    asm volatile("cp.async.cg.shared.global [%0], [%1], 16;" :: "r"(dst), "l"(src))
#define CP_COMMIT()  asm volatile("cp.async.commit_group;" ::: "memory")
#define CP_WAIT(n)   asm volatile("cp.async.wait_group %0;" :: "n"(n) : "memory")

#define LDSM_X4(r0, r1, r2, r3, addr) \
    asm volatile("ldmatrix.sync.aligned.m8n8.x4.shared.b16 {%0,%1,%2,%3}, [%4];" \
        : "=r"(r0), "=r"(r1), "=r"(r2), "=r"(r3) : "r"(addr))

static __device__ __forceinline__ void mma_tf32(float& c0, float& c1, float& c2, float& c3,
                                                uint32_t a0, uint32_t a1, uint32_t a2, uint32_t a3,
                                                uint32_t b0, uint32_t b1) {
    asm volatile(
        "mma.sync.aligned.m16n8k8.row.col.f32.tf32.tf32.f32 "
        "{%0,%1,%2,%3}, {%4,%5,%6,%7}, {%8,%9}, {%0,%1,%2,%3};"
        : "+f"(c0), "+f"(c1), "+f"(c2), "+f"(c3)
        : "r"(a0), "r"(a1), "r"(a2), "r"(a3), "r"(b0), "r"(b1));
}

// ---------------- init ----------------
__global__ void init_kernel() {
    int t = threadIdx.x;
    if (t < MC) g_counts[t] = 0.0f;
    if (t == 0) g_sumsq = 0.0f;
}

// ---------------- exact row norms (bitwise-R1 arithmetic) ----------------
__global__ void norms_kernel(const float* __restrict__ src, int which) {
    int warp = threadIdx.x >> 5, lane = threadIdx.x & 31;
    int row = blockIdx.x * 8 + warp;
    const float4* r4 = (const float4*)(src + ((size_t)row << 8));
    float s = 0.0f;
#pragma unroll
    for (int j = 0; j < 2; ++j) {
        float4 v = r4[lane + 32 * j];
        s += v.x * v.x + v.y * v.y + v.z * v.z + v.w * v.w;
    }
#pragma unroll
    for (int o = 16; o > 0; o >>= 1) s += __shfl_xor_sync(0xffffffffu, s, o);
    if (lane == 0) {
        if (which) g_normE[row] = s; else g_normX[row] = s;
    }
}

// ---------------- 16-warp TF32 GEMM (raw-f32 inputs, ldmatrix) + smem best-2 sketch ----------------
// warp grid 2(M) x 8(N); warp tile 64x32; per-thread acc 4x4x4
__global__ __launch_bounds__(512, 1)
void mma_argmin_kernel(const float* __restrict__ x, const float* __restrict__ emb) {
    extern __shared__ char smem[];
    uint32_t sb = s2u(smem);
    float* sne = (float*)(smem + OFF_SNE);
    float* sV1 = (float*)(smem + OFF_RED);          // [32][128]
    float* sV2 = sV1 + 4096;
    int*   sI1 = (int*)(sV2 + 4096);
    int*   sI2 = sI1 + 4096;

    int tid = threadIdx.x, wid = tid >> 5, lane = tid & 31;
    int warp_m = wid & 1, warp_n = wid >> 1;        // 2 x 8
    int lg = lane >> 2, lt = lane & 3;
    int row0 = blockIdx.x * BM;
    int slot = warp_n * 4 + lt;                     // 32 slots

    for (int i = tid; i < MC; i += 512) sne[i] = g_normE[i];
    for (int i = tid; i < 4096; i += 512) {
        sV1[i] = FINF; sV2[i] = FINF; sI1[i] = IMAX; sI2[i] = IMAX;
    }

    float nx8[8];
#pragma unroll
    for (int mt = 0; mt < 4; ++mt)
#pragma unroll
        for (int i = 0; i < 2; ++i)
            nx8[mt * 2 + i] = g_normX[row0 + warp_m * 64 + mt * 16 + i * 8 + lg];

    float acc[4][4][4];
#pragma unroll
    for (int mt = 0; mt < 4; ++mt)
#pragma unroll
        for (int n8 = 0; n8 < 4; ++n8)
#pragma unroll
            for (int q = 0; q < 4; ++q) acc[mt][n8][q] = 0.0f;

    // ldmatrix per-lane base offsets (computed once)
    int grp = lane >> 3, lr = lane & 7;
    uint32_t aOff[4];
#pragma unroll
    for (int mt = 0; mt < 4; ++mt)
        aOff[mt] = (uint32_t)((warp_m * 64 + mt * 16 + lr + (grp & 1) * 8) * LDPB)
                 + (uint32_t)((grp >> 1) * 16);
    uint32_t bOff = (uint32_t)A_BYTES
                  + (uint32_t)((warp_n * 32 + grp * 8 + lr) * LDPB);

    // cp.async loaders: A = 1024 16B-segs (2/thread), B = 2048 (4/thread)
    int a_r = tid >> 2, a_s = (tid & 3) * 2;        // A row, first seg
    int b_r = tid >> 1, b_s = (tid & 1) * 4;        // B row, first seg
    auto load_chunk = [&](int c) {
        int nt = c >> 3, kc = c & 7;
        int kbase = kc * KC;
        uint32_t stage = sb + OFF_STAGE + (c & 1) * STAGE_BYTES;
        const float* asrc = x + ((size_t)(row0 + a_r) << 8) + kbase + a_s * 4;
        uint32_t adst = stage + a_r * LDPB + a_s * 16;
        CP_ASYNC16(adst,      asrc);
        CP_ASYNC16(adst + 16, asrc + 4);
        const float* bsrc = emb + ((size_t)(nt * BN + b_r) << 8) + kbase + b_s * 4;
        uint32_t bdst = stage + A_BYTES + b_r * LDPB + b_s * 16;
#pragma unroll
        for (int j = 0; j < 4; ++j) CP_ASYNC16(bdst + j * 16, bsrc + j * 4);
    };

    __syncthreads();   // sne/red ready
    load_chunk(0); CP_COMMIT();

    for (int c = 0; c < NCHUNKS; ++c) {
        if (c + 1 < NCHUNKS) { load_chunk(c + 1); CP_COMMIT(); CP_WAIT(1); }
        else CP_WAIT(0);
        __syncthreads();

        uint32_t stageAddr = sb + OFF_STAGE + (c & 1) * STAGE_BYTES;

#pragma unroll
        for (int ks = 0; ks < 4; ++ks) {
            uint32_t kb = ks * 32;
            uint32_t a[4][4], b0[4], b1[4];
#pragma unroll
            for (int mt = 0; mt < 4; ++mt)
                LDSM_X4(a[mt][0], a[mt][1], a[mt][2], a[mt][3],
                        stageAddr + aOff[mt] + kb);
            LDSM_X4(b0[0], b0[1], b0[2], b0[3], stageAddr + bOff + kb);
            LDSM_X4(b1[0], b1[1], b1[2], b1[3], stageAddr + bOff + kb + 16);
#pragma unroll
            for (int mt = 0; mt < 4; ++mt)
#pragma unroll
                for (int n8 = 0; n8 < 4; ++n8)
                    mma_tf32(acc[mt][n8][0], acc[mt][n8][1], acc[mt][n8][2], acc[mt][n8][3],
                             a[mt][0], a[mt][1], a[mt][2], a[mt][3], b0[n8], b1[n8]);
        }

        if ((c & 7) == 7) {
            int nt = c >> 3;
#pragma unroll
            for (int mt = 0; mt < 4; ++mt)
#pragma unroll
                for (int i = 0; i < 2; ++i) {
                    int rl = warp_m * 64 + mt * 16 + i * 8 + lg;
                    float nx = nx8[mt * 2 + i];
                    float tv1 = FINF, tv2 = FINF; int ti1 = IMAX, ti2 = IMAX;
#pragma unroll
                    for (int n8 = 0; n8 < 4; ++n8) {
                        int cbase = nt * BN + warp_n * 32 + n8 * 8 + 2 * lt;
#pragma unroll
                        for (int q = 0; q < 2; ++q) {
                            float dot = acc[mt][n8][i * 2 + q];
                            float d = (sne[cbase + q] + nx) - 2.0f * dot;
                            int cc = cbase + q;
                            if (d < tv1 || (d == tv1 && cc < ti1)) {
                                tv2 = tv1; ti2 = ti1; tv1 = d; ti1 = cc;
                            } else if (d < tv2 || (d == tv2 && cc < ti2)) {
                                tv2 = d; ti2 = cc;
                            }
                        }
                    }
                    int o = slot * 128 + rl;
                    float mv1 = sV1[o], mv2 = sV2[o]; int mi1 = sI1[o], mi2 = sI2[o];
                    if (tv1 < mv1 || (tv1 == mv1 && ti1 < mi1)) {
                        mv2 = mv1; mi2 = mi1; mv1 = tv1; mi1 = ti1;
                    } else if (tv1 < mv2 || (tv1 == mv2 && ti1 < mi2)) {
                        mv2 = tv1; mi2 = ti1;
                    }
                    if (tv2 < mv1 || (tv2 == mv1 && ti2 < mi1)) {
                        mv2 = mv1; mi2 = mi1; mv1 = tv2; mi1 = ti2;
                    } else if (tv2 < mv2 || (tv2 == mv2 && ti2 < mi2)) {
                        mv2 = tv2; mi2 = ti2;
                    }
                    sV1[o] = mv1; sV2[o] = mv2; sI1[o] = mi1; sI2[o] = mi2;
                }
#pragma unroll
            for (int mt = 0; mt < 4; ++mt)
#pragma unroll
                for (int n8 = 0; n8 < 4; ++n8)
#pragma unroll
                    for (int q = 0; q < 4; ++q) acc[mt][n8][q] = 0.0f;
        }
        __syncthreads();   // all reads of stage (c&1) done before overwrite
    }

    // per-row top-NCAND of 32 slots x best-2 = 64 candidates
    if (tid < BM) {
        unsigned usedA = 0, usedB = 0;
#pragma unroll 1
        for (int sel = 0; sel < NCAND; ++sel) {
            float bv = FINF; int bi = IMAX; int bs = 0; int barr = 0;
            for (int s = 0; s < 32; ++s) {
                float v1 = sV1[s * 128 + tid]; int i1 = sI1[s * 128 + tid];
                float v2 = sV2[s * 128 + tid]; int i2 = sI2[s * 128 + tid];
                bool okA = !((usedA >> s) & 1u), okB = !((usedB >> s) & 1u);
                if (okA && (v1 < bv || (v1 == bv && i1 < bi))) { bv = v1; bi = i1; bs = s; barr = 0; }
                if (okB && (v2 < bv || (v2 == bv && i2 < bi))) { bv = v2; bi = i2; bs = s; barr = 1; }
            }
            if (barr) usedB |= 1u << bs; else usedA |= 1u << bs;
            g_cand[(size_t)(row0 + tid) * NCAND + sel] = bi;
        }
    }
}

// ---------------- fused refine (SERIAL-chain exact fp32) + gather + loss + histogram ----------------
__global__ __launch_bounds__(128, 8)
void refine_gather_kernel(const float* __restrict__ x, const float* __restrict__ emb,
                          float* __restrict__ d_out, long long idx_off, int write_idx) {
    __shared__ float sx[4][D];            // x rows
    __shared__ float se[4][NCAND * ELD];  // candidate rows, stride ELD
    int warp = threadIdx.x >> 5, lane = threadIdx.x & 31;
    int row = blockIdx.x * 4 + warp;

    int ci = 0;
    if (lane < NCAND) ci = g_cand[(size_t)row * NCAND + lane];
    int cj[NCAND];
#pragma unroll
    for (int j = 0; j < NCAND; ++j) cj[j] = __shfl_sync(0xffffffffu, ci, j);

    const float4* x4 = (const float4*)(x + ((size_t)row << 8));
    float4 xv0 = x4[lane], xv1 = x4[lane + 32];
    *(float4*)&sx[warp][lane * 4]        = xv0;
    *(float4*)&sx[warp][128 + lane * 4]  = xv1;

#pragma unroll
    for (int j = 0; j < NCAND; ++j) {
        const float4* e4 = (const float4*)(emb + ((size_t)cj[j] << 8));
        *(float4*)&se[warp][j * ELD + lane * 4]       = __ldg(&e4[lane]);
        *(float4*)&se[warp][j * ELD + 128 + lane * 4] = __ldg(&e4[lane + 32]);
    }
    __syncwarp();

    float myd = FINF;
    if (lane < NCAND) {
        const float* xs = sx[warp];
        const float* es = &se[warp][lane * ELD];
        float dot = 0.0f;
#pragma unroll 8
        for (int k4 = 0; k4 < 64; ++k4) {
            float4 xv = *(const float4*)&xs[k4 * 4];
            float4 ev = *(const float4*)&es[k4 * 4];
            dot = fmarn(xv.x, ev.x, dot);
            dot = fmarn(xv.y, ev.y, dot);
            dot = fmarn(xv.z, ev.z, dot);
            dot = fmarn(xv.w, ev.w, dot);
        }
        myd = (g_normX[row] + g_normE[cj[lane]]) - 2.0f * dot;
    }
    float dv[NCAND];
#pragma unroll
    for (int j = 0; j < NCAND; ++j) dv[j] = __shfl_sync(0xffffffffu, myd, j);
    float bv = FINF; int bi = IMAX; int bj = 0;
#pragma unroll
    for (int j = 0; j < NCAND; ++j) {
        if (dv[j] < bv || (dv[j] == bv && cj[j] < bi)) { bv = dv[j]; bi = cj[j]; bj = j; }
    }
    if (lane == 0 && write_idx) d_out[idx_off + row] = (float)bi;

    const float* qs = &se[warp][bj * ELD];
    float4* o4 = (float4*)(d_out + ((size_t)row << 8));
    float s = 0.0f;
    {
        float4 q = *(const float4*)&qs[lane * 4];
        float4 o;
        o.x = xv0.x + (q.x - xv0.x); o.y = xv0.y + (q.y - xv0.y);
        o.z = xv0.z + (q.z - xv0.z); o.w = xv0.w + (q.w - xv0.w);
        o4[lane] = o;
        float dx = xv0.x - q.x, dy = xv0.y - q.y, dz = xv0.z - q.z, dw = xv0.w - q.w;
        s += dx * dx + dy * dy + dz * dz + dw * dw;
    }
    {
        float4 q = *(const float4*)&qs[128 + lane * 4];
        float4 o;
        o.x = xv1.x + (q.x - xv1.x); o.y = xv1.y + (q.y - xv1.y);
        o.z = xv1.z + (q.z - xv1.z); o.w = xv1.w + (q.w - xv1.w);
        o4[lane + 32] = o;
        float dx = xv1.x - q.x, dy = xv1.y - q.y, dz = xv1.z - q.z, dw = xv1.w - q.w;
        s += dx * dx + dy * dy + dz * dz + dw * dw;
    }
#pragma unroll
    for (int o = 16; o > 0; o >>= 1) s += __shfl_xor_sync(0xffffffffu, s, o);
    if (lane == 0) {
        atomicAdd(&g_sumsq, s);
        atomicAdd(&g_counts[bi], 1.0f);
    }
}

// ---------------- loss + perplexity ----------------
__global__ void finalize_kernel(float* __restrict__ d_out, long long loss_off,
                                long long perp_off) {
    __shared__ float red[1024];
    int t = threadIdx.x;
    float p = g_counts[t] * (1.0f / (float)NTOK);
    red[t] = p * logf(p + 1e-10f);
    __syncthreads();
    for (int s = 512; s > 0; s >>= 1) {
        if (t < s) red[t] += red[t + s];
        __syncthreads();
    }
    if (t == 0) {
        d_out[loss_off] = 0.25f * g_sumsq / ((float)NTOK * (float)D);
        d_out[perp_off] = expf(-red[0]);
    }
}

// ---------------- launch ----------------
extern "C" void kernel_launch(void* const* d_in, const int* in_sizes, int n_in,
                              void* d_out, int out_size) {
    const float* x   = (const float*)d_in[0];
    const float* emb = (const float*)d_in[1];
    float* out = (float*)d_out;

    int NT = in_sizes[0] / D;
    long long qn = (long long)in_sizes[0];
    long long loss_off = qn;
    long long idx_off  = qn + 1;
    long long perp_off = qn + 1 + NT;
    int full = (out_size >= (int)(qn + NT + 2)) ? 1 : 0;

    cudaFuncSetAttribute(mma_argmin_kernel, cudaFuncAttributeMaxDynamicSharedMemorySize,
                         SMEM_TOTAL);

    init_kernel<<<1, 1024>>>();
    norms_kernel<<<NT / 8, 256>>>(x, 0);
    norms_kernel<<<MC / 8, 256>>>(emb, 1);
    mma_argmin_kernel<<<NT / BM, 512, SMEM_TOTAL>>>(x, emb);
    refine_gather_kernel<<<NT / 4, 128>>>(x, emb, out, idx_off, full);
    if (full) finalize_kernel<<<1, 1024>>>(out, loss_off, perp_off);
}

// round 12
// speedup vs baseline: 1.5224x; 1.3684x over previous
#include <cuda_runtime.h>
#include <cstdint>
#include <math.h>

#define D        256
#define MC       1024
#define NTOK     65536
#define BM       128
#define BN       256
#define KC       64                       // bf16 elements per K-chunk
#define LDPB     144                      // row stride bytes (128 data + 16 pad)
#define A_BYTES  (BM * LDPB)              // 18432
#define B_BYTES  (BN * LDPB)              // 36864
#define STAGE_BYTES (A_BYTES + B_BYTES)   // 55296
#define OFF_SNE   0
#define OFF_RED   4096                    // 4 arrays [32][128] = 64KB
#define OFF_STAGE 69632
#define SMEM_TOTAL (OFF_STAGE + 2 * STAGE_BYTES)   // 180224
#define NCHUNKS  16                       // 4 nt * 4 kc
#define NCAND    4
#define FINF     3.4e38f
#define IMAX     0x7fffffff
#define ELD      260                      // candidate-row smem stride (floats)

// ---- scratch (static, no allocations) ----
__device__ __align__(16) uint32_t g_xb[NTOK * D / 2];   // bf16x2-packed x (32MB)
__device__ __align__(16) uint32_t g_eb[MC * D / 2];     // bf16x2-packed emb
__device__ float g_normX[NTOK];
__device__ float g_normE[MC];
__device__ int   g_cand[NTOK * NCAND];
__device__ float g_counts[MC];
__device__ float g_sumsq;

static __device__ __forceinline__ uint32_t s2u(const void* p) {
    uint32_t a;
    asm("{ .reg .u64 t; cvta.to.shared.u64 t, %1; cvt.u32.u64 %0, t; }" : "=r"(a) : "l"(p));
    return a;
}
static __device__ __forceinline__ float fmarn(float a, float b, float c) {
    float d;
    asm("fma.rn.f32 %0, %1, %2, %3;" : "=f"(d) : "f"(a), "f"(b), "f"(c));
    return d;
}
static __device__ __forceinline__ uint32_t bf2(float lo, float hi) {
    uint32_t r;
    asm("cvt.rn.bf16x2.f32 %0, %1, %2;" : "=r"(r) : "f"(hi), "f"(lo));
    return r;
}
#define CP_ASYNC16(dst, src) \
    asm volatile("cp.async.cg.shared.global [%0], [%1], 16;" :: "r"(dst), "l"(src))
#define CP_COMMIT()  asm volatile("cp.async.commit_group;" ::: "memory")
#define CP_WAIT(n)   asm volatile("cp.async.wait_group %0;" :: "n"(n) : "memory")

#define LDSM_X4(r0, r1, r2, r3, addr) \
    asm volatile("ldmatrix.sync.aligned.m8n8.x4.shared.b16 {%0,%1,%2,%3}, [%4];" \
        : "=r"(r0), "=r"(r1), "=r"(r2), "=r"(r3) : "r"(addr))

static __device__ __forceinline__ void mma_bf16(float& c0, float& c1, float& c2, float& c3,
                                                uint32_t a0, uint32_t a1, uint32_t a2, uint32_t a3,
                                                uint32_t b0, uint32_t b1) {
    asm volatile(
        "mma.sync.aligned.m16n8k16.row.col.f32.bf16.bf16.f32 "
        "{%0,%1,%2,%3}, {%4,%5,%6,%7}, {%8,%9}, {%0,%1,%2,%3};"
        : "+f"(c0), "+f"(c1), "+f"(c2), "+f"(c3)
        : "r"(a0), "r"(a1), "r"(a2), "r"(a3), "r"(b0), "r"(b1));
}

// ---------------- init ----------------
__global__ void init_kernel() {
    int t = threadIdx.x;
    if (t < MC) g_counts[t] = 0.0f;
    if (t == 0) g_sumsq = 0.0f;
}

// ---------------- bf16 convert + exact row norms (bitwise-R1 norm arithmetic) ----------------
__global__ void convert_kernel(const float* __restrict__ src, int which) {
    int warp = threadIdx.x >> 5, lane = threadIdx.x & 31;
    int row = blockIdx.x * 8 + warp;
    uint32_t* dst = which ? g_eb : g_xb;
    const float4* r4 = (const float4*)(src + ((size_t)row << 8));
    float s = 0.0f;
#pragma unroll
    for (int j = 0; j < 2; ++j) {
        float4 v = r4[lane + 32 * j];
        dst[(size_t)row * 128 + j * 64 + lane * 2]     = bf2(v.x, v.y);
        dst[(size_t)row * 128 + j * 64 + lane * 2 + 1] = bf2(v.z, v.w);
        s += v.x * v.x + v.y * v.y + v.z * v.z + v.w * v.w;
    }
#pragma unroll
    for (int o = 16; o > 0; o >>= 1) s += __shfl_xor_sync(0xffffffffu, s, o);
    if (lane == 0) {
        if (which) g_normE[row] = s; else g_normX[row] = s;
    }
}

// ---------------- 16-warp BF16 GEMM (m16n8k16, ldmatrix) + smem best-2 sketch ----------------
// warp grid 2(M) x 8(N); warp tile 64x32; per-thread acc 4x4x4
__global__ __launch_bounds__(512, 1)
void mma_argmin_kernel() {
    extern __shared__ char smem[];
    uint32_t sb = s2u(smem);
    float* sne = (float*)(smem + OFF_SNE);
    float* sV1 = (float*)(smem + OFF_RED);          // [32][128]
    float* sV2 = sV1 + 4096;
    int*   sI1 = (int*)(sV2 + 4096);
    int*   sI2 = sI1 + 4096;

    int tid = threadIdx.x, wid = tid >> 5, lane = tid & 31;
    int warp_m = wid & 1, warp_n = wid >> 1;        // 2 x 8
    int lg = lane >> 2, lt = lane & 3;
    int row0 = blockIdx.x * BM;
    int slot = warp_n * 4 + lt;                     // 32 slots

    for (int i = tid; i < MC; i += 512) sne[i] = g_normE[i];
    for (int i = tid; i < 4096; i += 512) {
        sV1[i] = FINF; sV2[i] = FINF; sI1[i] = IMAX; sI2[i] = IMAX;
    }

    float nx8[8];
#pragma unroll
    for (int mt = 0; mt < 4; ++mt)
#pragma unroll
        for (int i = 0; i < 2; ++i)
            nx8[mt * 2 + i] = g_normX[row0 + warp_m * 64 + mt * 16 + i * 8 + lg];

    float acc[4][4][4];
#pragma unroll
    for (int mt = 0; mt < 4; ++mt)
#pragma unroll
        for (int n8 = 0; n8 < 4; ++n8)
#pragma unroll
            for (int q = 0; q < 4; ++q) acc[mt][n8][q] = 0.0f;

    // ldmatrix per-lane base offsets (m16n8k16 bf16; same pattern as validated tf32 map)
    int grp = lane >> 3, lr = lane & 7;
    uint32_t aOff[4];
#pragma unroll
    for (int mt = 0; mt < 4; ++mt)
        aOff[mt] = (uint32_t)((warp_m * 64 + mt * 16 + lr + (grp & 1) * 8) * LDPB)
                 + (uint32_t)((grp >> 1) * 16);     // 16B = 8 bf16 (k-half)
    uint32_t bOff = (uint32_t)A_BYTES
                  + (uint32_t)((warp_n * 32 + grp * 8 + lr) * LDPB);

    // cp.async loaders (byte addressed): A 1024 segs (2/thread), B 2048 (4/thread)
    int a_r = tid >> 2, a_s = (tid & 3) * 2;        // A row (4 thr/row), first seg
    int b_r = tid >> 1, b_s = (tid & 1) * 4;        // B row (2 thr/row), first seg
    auto load_chunk = [&](int c) {
        int nt = c >> 2, kc = c & 3;
        int kbyte = kc * (KC * 2);                  // 128B per chunk per row
        uint32_t stage = sb + OFF_STAGE + (c & 1) * STAGE_BYTES;
        const char* asrc = (const char*)g_xb + ((size_t)(row0 + a_r) << 9) + kbyte + a_s * 16;
        uint32_t adst = stage + a_r * LDPB + a_s * 16;
        CP_ASYNC16(adst,      asrc);
        CP_ASYNC16(adst + 16, asrc + 16);
        const char* bsrc = (const char*)g_eb + ((size_t)(nt * BN + b_r) << 9) + kbyte + b_s * 16;
        uint32_t bdst = stage + A_BYTES + b_r * LDPB + b_s * 16;
#pragma unroll
        for (int j = 0; j < 4; ++j) CP_ASYNC16(bdst + j * 16, bsrc + j * 16);
    };

    __syncthreads();   // sne/red ready
    load_chunk(0); CP_COMMIT();

    for (int c = 0; c < NCHUNKS; ++c) {
        if (c + 1 < NCHUNKS) { load_chunk(c + 1); CP_COMMIT(); CP_WAIT(1); }
        else CP_WAIT(0);
        __syncthreads();

        uint32_t stageAddr = sb + OFF_STAGE + (c & 1) * STAGE_BYTES;

#pragma unroll
        for (int ks = 0; ks < 4; ++ks) {            // 4 x k16 per chunk
            uint32_t kb = ks * 32;                  // 16 bf16 = 32 bytes
            uint32_t a[4][4], b0[4], b1[4];
#pragma unroll
            for (int mt = 0; mt < 4; ++mt)
                LDSM_X4(a[mt][0], a[mt][1], a[mt][2], a[mt][3],
                        stageAddr + aOff[mt] + kb);
            LDSM_X4(b0[0], b0[1], b0[2], b0[3], stageAddr + bOff + kb);
            LDSM_X4(b1[0], b1[1], b1[2], b1[3], stageAddr + bOff + kb + 16);
#pragma unroll
            for (int mt = 0; mt < 4; ++mt)
#pragma unroll
                for (int n8 = 0; n8 < 4; ++n8)
                    mma_bf16(acc[mt][n8][0], acc[mt][n8][1], acc[mt][n8][2], acc[mt][n8][3],
                             a[mt][0], a[mt][1], a[mt][2], a[mt][3], b0[n8], b1[n8]);
        }

        if ((c & 3) == 3) {
            int nt = c >> 2;
#pragma unroll
            for (int mt = 0; mt < 4; ++mt)
#pragma unroll
                for (int i = 0; i < 2; ++i) {
                    int rl = warp_m * 64 + mt * 16 + i * 8 + lg;
                    float nx = nx8[mt * 2 + i];
                    float tv1 = FINF, tv2 = FINF; int ti1 = IMAX, ti2 = IMAX;
#pragma unroll
                    for (int n8 = 0; n8 < 4; ++n8) {
                        int cbase = nt * BN + warp_n * 32 + n8 * 8 + 2 * lt;
#pragma unroll
                        for (int q = 0; q < 2; ++q) {
                            float dot = acc[mt][n8][i * 2 + q];
                            float d = (sne[cbase + q] + nx) - 2.0f * dot;
                            int cc = cbase + q;
                            if (d < tv1 || (d == tv1 && cc < ti1)) {
                                tv2 = tv1; ti2 = ti1; tv1 = d; ti1 = cc;
                            } else if (d < tv2 || (d == tv2 && cc < ti2)) {
                                tv2 = d; ti2 = cc;
                            }
                        }
                    }
                    int o = slot * 128 + rl;
                    float mv1 = sV1[o], mv2 = sV2[o]; int mi1 = sI1[o], mi2 = sI2[o];
                    if (tv1 < mv1 || (tv1 == mv1 && ti1 < mi1)) {
                        mv2 = mv1; mi2 = mi1; mv1 = tv1; mi1 = ti1;
                    } else if (tv1 < mv2 || (tv1 == mv2 && ti1 < mi2)) {
                        mv2 = tv1; mi2 = ti1;
                    }
                    if (tv2 < mv1 || (tv2 == mv1 && ti2 < mi1)) {
                        mv2 = mv1; mi2 = mi1; mv1 = tv2; mi1 = ti2;
                    } else if (tv2 < mv2 || (tv2 == mv2 && ti2 < mi2)) {
                        mv2 = tv2; mi2 = ti2;
                    }
                    sV1[o] = mv1; sV2[o] = mv2; sI1[o] = mi1; sI2[o] = mi2;
                }
#pragma unroll
            for (int mt = 0; mt < 4; ++mt)
#pragma unroll
                for (int n8 = 0; n8 < 4; ++n8)
#pragma unroll
                    for (int q = 0; q < 4; ++q) acc[mt][n8][q] = 0.0f;
        }
        __syncthreads();   // all reads of stage (c&1) done before overwrite
    }

    // per-row top-NCAND of 32 slots x best-2 = 64 candidates
    if (tid < BM) {
        unsigned usedA = 0, usedB = 0;
#pragma unroll 1
        for (int sel = 0; sel < NCAND; ++sel) {
            float bv = FINF; int bi = IMAX; int bs = 0; int barr = 0;
            for (int s = 0; s < 32; ++s) {
                float v1 = sV1[s * 128 + tid]; int i1 = sI1[s * 128 + tid];
                float v2 = sV2[s * 128 + tid]; int i2 = sI2[s * 128 + tid];
                bool okA = !((usedA >> s) & 1u), okB = !((usedB >> s) & 1u);
                if (okA && (v1 < bv || (v1 == bv && i1 < bi))) { bv = v1; bi = i1; bs = s; barr = 0; }
                if (okB && (v2 < bv || (v2 == bv && i2 < bi))) { bv = v2; bi = i2; bs = s; barr = 1; }
            }
            if (barr) usedB |= 1u << bs; else usedA |= 1u << bs;
            g_cand[(size_t)(row0 + tid) * NCAND + sel] = bi;
        }
    }
}

// ---------------- fused refine (SERIAL-chain exact fp32) + gather + loss + histogram ----------------
__global__ __launch_bounds__(128, 8)
void refine_gather_kernel(const float* __restrict__ x, const float* __restrict__ emb,
                          float* __restrict__ d_out, long long idx_off, int write_idx) {
    __shared__ float sx[4][D];            // x rows
    __shared__ float se[4][NCAND * ELD];  // candidate rows, stride ELD
    int warp = threadIdx.x >> 5, lane = threadIdx.x & 31;
    int row = blockIdx.x * 4 + warp;

    int ci = 0;
    if (lane < NCAND) ci = g_cand[(size_t)row * NCAND + lane];
    int cj[NCAND];
#pragma unroll
    for (int j = 0; j < NCAND; ++j) cj[j] = __shfl_sync(0xffffffffu, ci, j);

    const float4* x4 = (const float4*)(x + ((size_t)row << 8));
    float4 xv0 = x4[lane], xv1 = x4[lane + 32];
    *(float4*)&sx[warp][lane * 4]        = xv0;
    *(float4*)&sx[warp][128 + lane * 4]  = xv1;

#pragma unroll
    for (int j = 0; j < NCAND; ++j) {
        const float4* e4 = (const float4*)(emb + ((size_t)cj[j] << 8));
        *(float4*)&se[warp][j * ELD + lane * 4]       = __ldg(&e4[lane]);
        *(float4*)&se[warp][j * ELD + 128 + lane * 4] = __ldg(&e4[lane + 32]);
    }
    __syncwarp();

    float myd = FINF;
    if (lane < NCAND) {
        const float* xs = sx[warp];
        const float* es = &se[warp][lane * ELD];
        float dot = 0.0f;
#pragma unroll 8
        for (int k4 = 0; k4 < 64; ++k4) {
            float4 xv = *(const float4*)&xs[k4 * 4];
            float4 ev = *(const float4*)&es[k4 * 4];
            dot = fmarn(xv.x, ev.x, dot);
            dot = fmarn(xv.y, ev.y, dot);
            dot = fmarn(xv.z, ev.z, dot);
            dot = fmarn(xv.w, ev.w, dot);
        }
        myd = (g_normX[row] + g_normE[cj[lane]]) - 2.0f * dot;
    }
    float dv[NCAND];
#pragma unroll
    for (int j = 0; j < NCAND; ++j) dv[j] = __shfl_sync(0xffffffffu, myd, j);
    float bv = FINF; int bi = IMAX; int bj = 0;
#pragma unroll
    for (int j = 0; j < NCAND; ++j) {
        if (dv[j] < bv || (dv[j] == bv && cj[j] < bi)) { bv = dv[j]; bi = cj[j]; bj = j; }
    }
    if (lane == 0 && write_idx) d_out[idx_off + row] = (float)bi;

    const float* qs = &se[warp][bj * ELD];
    float4* o4 = (float4*)(d_out + ((size_t)row << 8));
    float s = 0.0f;
    {
        float4 q = *(const float4*)&qs[lane * 4];
        float4 o;
        o.x = xv0.x + (q.x - xv0.x); o.y = xv0.y + (q.y - xv0.y);
        o.z = xv0.z + (q.z - xv0.z); o.w = xv0.w + (q.w - xv0.w);
        o4[lane] = o;
        float dx = xv0.x - q.x, dy = xv0.y - q.y, dz = xv0.z - q.z, dw = xv0.w - q.w;
        s += dx * dx + dy * dy + dz * dz + dw * dw;
    }
    {
        float4 q = *(const float4*)&qs[128 + lane * 4];
        float4 o;
        o.x = xv1.x + (q.x - xv1.x); o.y = xv1.y + (q.y - xv1.y);
        o.z = xv1.z + (q.z - xv1.z); o.w = xv1.w + (q.w - xv1.w);
        o4[lane + 32] = o;
        float dx = xv1.x - q.x, dy = xv1.y - q.y, dz = xv1.z - q.z, dw = xv1.w - q.w;
        s += dx * dx + dy * dy + dz * dz + dw * dw;
    }
#pragma unroll
    for (int o = 16; o > 0; o >>= 1) s += __shfl_xor_sync(0xffffffffu, s, o);
    if (lane == 0) {
        atomicAdd(&g_sumsq, s);
        atomicAdd(&g_counts[bi], 1.0f);
    }
}

// ---------------- loss + perplexity ----------------
__global__ void finalize_kernel(float* __restrict__ d_out, long long loss_off,
                                long long perp_off) {
    __shared__ float red[1024];
    int t = threadIdx.x;
    float p = g_counts[t] * (1.0f / (float)NTOK);
    red[t] = p * logf(p + 1e-10f);
    __syncthreads();
    for (int s = 512; s > 0; s >>= 1) {
        if (t < s) red[t] += red[t + s];
        __syncthreads();
    }
    if (t == 0) {
        d_out[loss_off] = 0.25f * g_sumsq / ((float)NTOK * (float)D);
        d_out[perp_off] = expf(-red[0]);
    }
}

// ---------------- launch ----------------
extern "C" void kernel_launch(void* const* d_in, const int* in_sizes, int n_in,
                              void* d_out, int out_size) {
    const float* x   = (const float*)d_in[0];
    const float* emb = (const float*)d_in[1];
    float* out = (float*)d_out;

    int NT = in_sizes[0] / D;
    long long qn = (long long)in_sizes[0];
    long long loss_off = qn;
    long long idx_off  = qn + 1;
    long long perp_off = qn + 1 + NT;
    int full = (out_size >= (int)(qn + NT + 2)) ? 1 : 0;

    cudaFuncSetAttribute(mma_argmin_kernel, cudaFuncAttributeMaxDynamicSharedMemorySize,
                         SMEM_TOTAL);

    init_kernel<<<1, 1024>>>();
    convert_kernel<<<NT / 8, 256>>>(x, 0);
    convert_kernel<<<MC / 8, 256>>>(emb, 1);
    mma_argmin_kernel<<<NT / BM, 512, SMEM_TOTAL>>>();
    refine_gather_kernel<<<NT / 4, 128>>>(x, emb, out, idx_off, full);
    if (full) finalize_kernel<<<1, 1024>>>(out, loss_off, perp_off);
}

// round 13
// speedup vs baseline: 1.8820x; 1.2362x over previous
#include <cuda_runtime.h>
#include <cstdint>
#include <math.h>

#define D        256
#define MC       1024
#define NTOK     65536
#define BM       128
#define BN       256
#define LDPB     144                      // row stride bytes (128 data + 16 pad)
#define A_BYTES  (BM * LDPB)              // 18432
#define B_BYTES  (BN * LDPB)              // 36864
#define STAGE_BYTES (A_BYTES + B_BYTES)   // 55296
#define OFF_SNE   0                       // 4KB code norms
#define OFF_SSE   4096                    // 4KB code scales
#define OFF_RED   8192                    // 4 arrays [32][128] = 64KB
#define OFF_STAGE 73728
#define SMEM_TOTAL (OFF_STAGE + 2 * STAGE_BYTES)   // 184320
#define NCHUNKS  8                        // 4 nt * 2 kc (128B of K per chunk-row)
#define NCAND    4
#define FINF     3.4e38f
#define IMAX     0x7fffffff
#define ELD      260                      // candidate-row smem stride (floats)

// ---- scratch (static, no allocations) ----
__device__ __align__(16) uint32_t g_xq[NTOK * D / 4];   // s8x4-packed x (16MB)
__device__ __align__(16) uint32_t g_eq[MC * D / 4];     // s8x4-packed emb
__device__ float g_normX[NTOK];
__device__ float g_normE[MC];
__device__ float g_sx[NTOK];              // per-row dequant scale
__device__ float g_se[MC];                // per-code dequant scale
__device__ int   g_cand[NTOK * NCAND];
__device__ float g_counts[MC];
__device__ float g_sumsq;

static __device__ __forceinline__ uint32_t s2u(const void* p) {
    uint32_t a;
    asm("{ .reg .u64 t; cvta.to.shared.u64 t, %1; cvt.u32.u64 %0, t; }" : "=r"(a) : "l"(p));
    return a;
}
static __device__ __forceinline__ float fmarn(float a, float b, float c) {
    float d;
    asm("fma.rn.f32 %0, %1, %2, %3;" : "=f"(d) : "f"(a), "f"(b), "f"(c));
    return d;
}
#define CP_ASYNC16(dst, src) \
    asm volatile("cp.async.cg.shared.global [%0], [%1], 16;" :: "r"(dst), "l"(src))
#define CP_COMMIT()  asm volatile("cp.async.commit_group;" ::: "memory")
#define CP_WAIT(n)   asm volatile("cp.async.wait_group %0;" :: "n"(n) : "memory")

#define LDSM_X4(r0, r1, r2, r3, addr) \
    asm volatile("ldmatrix.sync.aligned.m8n8.x4.shared.b16 {%0,%1,%2,%3}, [%4];" \
        : "=r"(r0), "=r"(r1), "=r"(r2), "=r"(r3) : "r"(addr))

static __device__ __forceinline__ void imma(int& c0, int& c1, int& c2, int& c3,
                                            uint32_t a0, uint32_t a1, uint32_t a2, uint32_t a3,
                                            uint32_t b0, uint32_t b1) {
    asm volatile(
        "mma.sync.aligned.m16n8k32.row.col.s32.s8.s8.s32 "
        "{%0,%1,%2,%3}, {%4,%5,%6,%7}, {%8,%9}, {%0,%1,%2,%3};"
        : "+r"(c0), "+r"(c1), "+r"(c2), "+r"(c3)
        : "r"(a0), "r"(a1), "r"(a2), "r"(a3), "r"(b0), "r"(b1));
}

// ---------------- init ----------------
__global__ void init_kernel() {
    int t = threadIdx.x;
    if (t < MC) g_counts[t] = 0.0f;
    if (t == 0) g_sumsq = 0.0f;
}

// ---------------- s8 quantize + exact row norms (bitwise-R1 norm arithmetic) ----------------
__global__ void convert_kernel(const float* __restrict__ src, int which) {
    int warp = threadIdx.x >> 5, lane = threadIdx.x & 31;
    int row = blockIdx.x * 8 + warp;
    uint32_t* dst = which ? g_eq : g_xq;
    const float4* r4 = (const float4*)(src + ((size_t)row << 8));
    float4 v0 = r4[lane], v1 = r4[lane + 32];

    // exact norm (same arithmetic order as all passing rounds)
    float s = 0.0f;
    s += v0.x * v0.x + v0.y * v0.y + v0.z * v0.z + v0.w * v0.w;
    s += v1.x * v1.x + v1.y * v1.y + v1.z * v1.z + v1.w * v1.w;
#pragma unroll
    for (int o = 16; o > 0; o >>= 1) s += __shfl_xor_sync(0xffffffffu, s, o);

    // row max-abs
    float m = fabsf(v0.x);
    m = fmaxf(m, fabsf(v0.y)); m = fmaxf(m, fabsf(v0.z)); m = fmaxf(m, fabsf(v0.w));
    m = fmaxf(m, fabsf(v1.x)); m = fmaxf(m, fabsf(v1.y));
    m = fmaxf(m, fabsf(v1.z)); m = fmaxf(m, fabsf(v1.w));
#pragma unroll
    for (int o = 16; o > 0; o >>= 1) m = fmaxf(m, __shfl_xor_sync(0xffffffffu, m, o));
    m = fmaxf(m, 1e-30f);
    float inv = 127.0f / m;

    uint32_t p0, p1;
    {
        int a = __float2int_rn(v0.x * inv), b = __float2int_rn(v0.y * inv);
        int c = __float2int_rn(v0.z * inv), d = __float2int_rn(v0.w * inv);
        p0 = (a & 255) | ((b & 255) << 8) | ((c & 255) << 16) | ((d & 255) << 24);
        a = __float2int_rn(v1.x * inv); b = __float2int_rn(v1.y * inv);
        c = __float2int_rn(v1.z * inv); d = __float2int_rn(v1.w * inv);
        p1 = (a & 255) | ((b & 255) << 8) | ((c & 255) << 16) | ((d & 255) << 24);
    }
    dst[(size_t)row * 64 + lane]      = p0;
    dst[(size_t)row * 64 + lane + 32] = p1;

    if (lane == 0) {
        if (which) { g_normE[row] = s; g_se[row] = m * (1.0f / 127.0f); }
        else       { g_normX[row] = s; g_sx[row] = m * (1.0f / 127.0f); }
    }
}

// ---------------- 16-warp S8 IMMA GEMM (m16n8k32, ldmatrix) + smem best-2 sketch ----------------
// warp grid 2(M) x 8(N); warp tile 64x32; per-thread acc 4x4x4 (s32)
__global__ __launch_bounds__(512, 1)
void mma_argmin_kernel() {
    extern __shared__ char smem[];
    uint32_t sb = s2u(smem);
    float* sne = (float*)(smem + OFF_SNE);
    float* sse = (float*)(smem + OFF_SSE);
    float* sV1 = (float*)(smem + OFF_RED);          // [32][128]
    float* sV2 = sV1 + 4096;
    int*   sI1 = (int*)(sV2 + 4096);
    int*   sI2 = sI1 + 4096;

    int tid = threadIdx.x, wid = tid >> 5, lane = tid & 31;
    int warp_m = wid & 1, warp_n = wid >> 1;        // 2 x 8
    int lg = lane >> 2, lt = lane & 3;
    int row0 = blockIdx.x * BM;
    int slot = warp_n * 4 + lt;                     // 32 slots

    for (int i = tid; i < MC; i += 512) { sne[i] = g_normE[i]; sse[i] = g_se[i]; }
    for (int i = tid; i < 4096; i += 512) {
        sV1[i] = FINF; sV2[i] = FINF; sI1[i] = IMAX; sI2[i] = IMAX;
    }

    float nx8[8], sx8[8];
#pragma unroll
    for (int mt = 0; mt < 4; ++mt)
#pragma unroll
        for (int i = 0; i < 2; ++i) {
            int r = row0 + warp_m * 64 + mt * 16 + i * 8 + lg;
            nx8[mt * 2 + i] = g_normX[r];
            sx8[mt * 2 + i] = g_sx[r];
        }

    int acc[4][4][4];
#pragma unroll
    for (int mt = 0; mt < 4; ++mt)
#pragma unroll
        for (int n8 = 0; n8 < 4; ++n8)
#pragma unroll
            for (int q = 0; q < 4; ++q) acc[mt][n8][q] = 0;

    // ldmatrix per-lane base offsets (byte-identical pattern to validated bf16 map)
    int grp = lane >> 3, lr = lane & 7;
    uint32_t aOff[4];
#pragma unroll
    for (int mt = 0; mt < 4; ++mt)
        aOff[mt] = (uint32_t)((warp_m * 64 + mt * 16 + lr + (grp & 1) * 8) * LDPB)
                 + (uint32_t)((grp >> 1) * 16);
    uint32_t bOff = (uint32_t)A_BYTES
                  + (uint32_t)((warp_n * 32 + grp * 8 + lr) * LDPB);

    // cp.async loaders: 128 bytes of K per row per chunk
    int a_r = tid >> 2, a_s = (tid & 3) * 2;        // A row (4 thr/row), first 16B seg
    int b_r = tid >> 1, b_s = (tid & 1) * 4;        // B row (2 thr/row), first seg
    auto load_chunk = [&](int c) {
        int nt = c >> 1, kc = c & 1;
        int kbyte = kc * 128;
        uint32_t stage = sb + OFF_STAGE + (c & 1) * STAGE_BYTES;
        const char* asrc = (const char*)g_xq + ((size_t)(row0 + a_r) << 8) + kbyte + a_s * 16;
        uint32_t adst = stage + a_r * LDPB + a_s * 16;
        CP_ASYNC16(adst,      asrc);
        CP_ASYNC16(adst + 16, asrc + 16);
        const char* bsrc = (const char*)g_eq + ((size_t)(nt * BN + b_r) << 8) + kbyte + b_s * 16;
        uint32_t bdst = stage + A_BYTES + b_r * LDPB + b_s * 16;
#pragma unroll
        for (int j = 0; j < 4; ++j) CP_ASYNC16(bdst + j * 16, bsrc + j * 16);
    };

    __syncthreads();   // sne/sse/red ready
    load_chunk(0); CP_COMMIT();

    for (int c = 0; c < NCHUNKS; ++c) {
        if (c + 1 < NCHUNKS) { load_chunk(c + 1); CP_COMMIT(); CP_WAIT(1); }
        else CP_WAIT(0);
        __syncthreads();

        uint32_t stageAddr = sb + OFF_STAGE + (c & 1) * STAGE_BYTES;

#pragma unroll
        for (int ks = 0; ks < 4; ++ks) {            // 4 x k32 per chunk
            uint32_t kb = ks * 32;                  // 32 s8 = 32 bytes
            uint32_t a[4][4], b0[4], b1[4];
#pragma unroll
            for (int mt = 0; mt < 4; ++mt)
                LDSM_X4(a[mt][0], a[mt][1], a[mt][2], a[mt][3],
                        stageAddr + aOff[mt] + kb);
            LDSM_X4(b0[0], b0[1], b0[2], b0[3], stageAddr + bOff + kb);
            LDSM_X4(b1[0], b1[1], b1[2], b1[3], stageAddr + bOff + kb + 16);
#pragma unroll
            for (int mt = 0; mt < 4; ++mt)
#pragma unroll
                for (int n8 = 0; n8 < 4; ++n8)
                    imma(acc[mt][n8][0], acc[mt][n8][1], acc[mt][n8][2], acc[mt][n8][3],
                         a[mt][0], a[mt][1], a[mt][2], a[mt][3], b0[n8], b1[n8]);
        }

        if ((c & 1) == 1) {
            int nt = c >> 1;
#pragma unroll
            for (int mt = 0; mt < 4; ++mt)
#pragma unroll
                for (int i = 0; i < 2; ++i) {
                    int rl = warp_m * 64 + mt * 16 + i * 8 + lg;
                    float nx = nx8[mt * 2 + i];
                    float sx = sx8[mt * 2 + i];
                    float tv1 = FINF, tv2 = FINF; int ti1 = IMAX, ti2 = IMAX;
#pragma unroll
                    for (int n8 = 0; n8 < 4; ++n8) {
                        int cbase = nt * BN + warp_n * 32 + n8 * 8 + 2 * lt;
#pragma unroll
                        for (int q = 0; q < 2; ++q) {
                            float dot = (float)acc[mt][n8][i * 2 + q] * (sx * sse[cbase + q]);
                            float d = (sne[cbase + q] + nx) - 2.0f * dot;
                            int cc = cbase + q;
                            if (d < tv1 || (d == tv1 && cc < ti1)) {
                                tv2 = tv1; ti2 = ti1; tv1 = d; ti1 = cc;
                            } else if (d < tv2 || (d == tv2 && cc < ti2)) {
                                tv2 = d; ti2 = cc;
                            }
                        }
                    }
                    int o = slot * 128 + rl;
                    float mv1 = sV1[o], mv2 = sV2[o]; int mi1 = sI1[o], mi2 = sI2[o];
                    if (tv1 < mv1 || (tv1 == mv1 && ti1 < mi1)) {
                        mv2 = mv1; mi2 = mi1; mv1 = tv1; mi1 = ti1;
                    } else if (tv1 < mv2 || (tv1 == mv2 && ti1 < mi2)) {
                        mv2 = tv1; mi2 = ti1;
                    }
                    if (tv2 < mv1 || (tv2 == mv1 && ti2 < mi1)) {
                        mv2 = mv1; mi2 = mi1; mv1 = tv2; mi1 = ti2;
                    } else if (tv2 < mv2 || (tv2 == mv2 && ti2 < mi2)) {
                        mv2 = tv2; mi2 = ti2;
                    }
                    sV1[o] = mv1; sV2[o] = mv2; sI1[o] = mi1; sI2[o] = mi2;
                }
#pragma unroll
            for (int mt = 0; mt < 4; ++mt)
#pragma unroll
                for (int n8 = 0; n8 < 4; ++n8)
#pragma unroll
                    for (int q = 0; q < 4; ++q) acc[mt][n8][q] = 0;
        }
        __syncthreads();   // all reads of stage (c&1) done before overwrite
    }

    // per-row top-NCAND of 32 slots x best-2 = 64 candidates
    if (tid < BM) {
        unsigned usedA = 0, usedB = 0;
#pragma unroll 1
        for (int sel = 0; sel < NCAND; ++sel) {
            float bv = FINF; int bi = IMAX; int bs = 0; int barr = 0;
            for (int s = 0; s < 32; ++s) {
                float v1 = sV1[s * 128 + tid]; int i1 = sI1[s * 128 + tid];
                float v2 = sV2[s * 128 + tid]; int i2 = sI2[s * 128 + tid];
                bool okA = !((usedA >> s) & 1u), okB = !((usedB >> s) & 1u);
                if (okA && (v1 < bv || (v1 == bv && i1 < bi))) { bv = v1; bi = i1; bs = s; barr = 0; }
                if (okB && (v2 < bv || (v2 == bv && i2 < bi))) { bv = v2; bi = i2; bs = s; barr = 1; }
            }
            if (barr) usedB |= 1u << bs; else usedA |= 1u << bs;
            g_cand[(size_t)(row0 + tid) * NCAND + sel] = bi;
        }
    }
}

// ---------------- fused refine (SERIAL-chain exact fp32) + gather + loss + histogram ----------------
__global__ __launch_bounds__(128, 8)
void refine_gather_kernel(const float* __restrict__ x, const float* __restrict__ emb,
                          float* __restrict__ d_out, long long idx_off, int write_idx) {
    __shared__ float sx[4][D];            // x rows
    __shared__ float se[4][NCAND * ELD];  // candidate rows, stride ELD
    int warp = threadIdx.x >> 5, lane = threadIdx.x & 31;
    int row = blockIdx.x * 4 + warp;

    int ci = 0;
    if (lane < NCAND) ci = g_cand[(size_t)row * NCAND + lane];
    int cj[NCAND];
#pragma unroll
    for (int j = 0; j < NCAND; ++j) cj[j] = __shfl_sync(0xffffffffu, ci, j);

    const float4* x4 = (const float4*)(x + ((size_t)row << 8));
    float4 xv0 = x4[lane], xv1 = x4[lane + 32];
    *(float4*)&sx[warp][lane * 4]        = xv0;
    *(float4*)&sx[warp][128 + lane * 4]  = xv1;

#pragma unroll
    for (int j = 0; j < NCAND; ++j) {
        const float4* e4 = (const float4*)(emb + ((size_t)cj[j] << 8));
        *(float4*)&se[warp][j * ELD + lane * 4]       = __ldg(&e4[lane]);
        *(float4*)&se[warp][j * ELD + 128 + lane * 4] = __ldg(&e4[lane + 32]);
    }
    __syncwarp();

    float myd = FINF;
    if (lane < NCAND) {
        const float* xs = sx[warp];
        const float* es = &se[warp][lane * ELD];
        float dot = 0.0f;
#pragma unroll 8
        for (int k4 = 0; k4 < 64; ++k4) {
            float4 xv = *(const float4*)&xs[k4 * 4];
            float4 ev = *(const float4*)&es[k4 * 4];
            dot = fmarn(xv.x, ev.x, dot);
            dot = fmarn(xv.y, ev.y, dot);
            dot = fmarn(xv.z, ev.z, dot);
            dot = fmarn(xv.w, ev.w, dot);
        }
        myd = (g_normX[row] + g_normE[cj[lane]]) - 2.0f * dot;
    }
    float dv[NCAND];
#pragma unroll
    for (int j = 0; j < NCAND; ++j) dv[j] = __shfl_sync(0xffffffffu, myd, j);
    float bv = FINF; int bi = IMAX; int bj = 0;
#pragma unroll
    for (int j = 0; j < NCAND; ++j) {
        if (dv[j] < bv || (dv[j] == bv && cj[j] < bi)) { bv = dv[j]; bi = cj[j]; bj = j; }
    }
    if (lane == 0 && write_idx) d_out[idx_off + row] = (float)bi;

    const float* qs = &se[warp][bj * ELD];
    float4* o4 = (float4*)(d_out + ((size_t)row << 8));
    float s = 0.0f;
    {
        float4 q = *(const float4*)&qs[lane * 4];
        float4 o;
        o.x = xv0.x + (q.x - xv0.x); o.y = xv0.y + (q.y - xv0.y);
        o.z = xv0.z + (q.z - xv0.z); o.w = xv0.w + (q.w - xv0.w);
        o4[lane] = o;
        float dx = xv0.x - q.x, dy = xv0.y - q.y, dz = xv0.z - q.z, dw = xv0.w - q.w;
        s += dx * dx + dy * dy + dz * dz + dw * dw;
    }
    {
        float4 q = *(const float4*)&qs[128 + lane * 4];
        float4 o;
        o.x = xv1.x + (q.x - xv1.x); o.y = xv1.y + (q.y - xv1.y);
        o.z = xv1.z + (q.z - xv1.z); o.w = xv1.w + (q.w - xv1.w);
        o4[lane + 32] = o;
        float dx = xv1.x - q.x, dy = xv1.y - q.y, dz = xv1.z - q.z, dw = xv1.w - q.w;
        s += dx * dx + dy * dy + dz * dz + dw * dw;
    }
#pragma unroll
    for (int o = 16; o > 0; o >>= 1) s += __shfl_xor_sync(0xffffffffu, s, o);
    if (lane == 0) {
        atomicAdd(&g_sumsq, s);
        atomicAdd(&g_counts[bi], 1.0f);
    }
}

// ---------------- loss + perplexity ----------------
__global__ void finalize_kernel(float* __restrict__ d_out, long long loss_off,
                                long long perp_off) {
    __shared__ float red[1024];
    int t = threadIdx.x;
    float p = g_counts[t] * (1.0f / (float)NTOK);
    red[t] = p * logf(p + 1e-10f);
    __syncthreads();
    for (int s = 512; s > 0; s >>= 1) {
        if (t < s) red[t] += red[t + s];
        __syncthreads();
    }
    if (t == 0) {
        d_out[loss_off] = 0.25f * g_sumsq / ((float)NTOK * (float)D);
        d_out[perp_off] = expf(-red[0]);
    }
}

// ---------------- launch ----------------
extern "C" void kernel_launch(void* const* d_in, const int* in_sizes, int n_in,
                              void* d_out, int out_size) {
    const float* x   = (const float*)d_in[0];
    const float* emb = (const float*)d_in[1];
    float* out = (float*)d_out;

    int NT = in_sizes[0] / D;
    long long qn = (long long)in_sizes[0];
    long long loss_off = qn;
    long long idx_off  = qn + 1;
    long long perp_off = qn + 1 + NT;
    int full = (out_size >= (int)(qn + NT + 2)) ? 1 : 0;

    cudaFuncSetAttribute(mma_argmin_kernel, cudaFuncAttributeMaxDynamicSharedMemorySize,
                         SMEM_TOTAL);

    init_kernel<<<1, 1024>>>();
    convert_kernel<<<NT / 8, 256>>>(x, 0);
    convert_kernel<<<MC / 8, 256>>>(emb, 1);
    mma_argmin_kernel<<<NT / BM, 512, SMEM_TOTAL>>>();
    refine_gather_kernel<<<NT / 4, 128>>>(x, emb, out, idx_off, full);
    if (full) finalize_kernel<<<1, 1024>>>(out, loss_off, perp_off);
}

// round 15
// speedup vs baseline: 1.9403x; 1.0310x over previous
#include <cuda_runtime.h>
#include <cstdint>
#include <math.h>

#define D        256
#define MC       1024
#define NTOK     65536
#define BM       128
#define BN       256
#define LDPB     144                      // B row stride bytes (128 data + 16 pad)
#define ALDPB    272                      // A row stride bytes (256 data + 16 pad)
#define A_RES    (BM * ALDPB)             // 34816 resident A tile
#define B_BYTES  (BN * LDPB)              // 36864 per B stage
#define OFF_SNE   0                       // 4KB code norms
#define OFF_SSE   4096                    // 4KB code scales
#define OFF_RED   8192                    // 4 arrays [32][128] = 64KB
#define OFF_A     73728
#define OFF_STAGE (OFF_A + A_RES)         // 108544
#define SMEM_TOTAL (OFF_STAGE + 3 * B_BYTES)   // 219136
#define NCHUNKS  8                        // 4 nt * 2 kc (128B of K per chunk-row)
#define NCAND    4
#define FINF     3.4e38f
#define IMAX     0x7fffffff
#define ELD      260                      // candidate-row smem stride (floats)

// ---- scratch (static, no allocations) ----
__device__ __align__(16) uint32_t g_xq[NTOK * D / 4];   // s8x4-packed x (16MB)
__device__ __align__(16) uint32_t g_eq[MC * D / 4];     // s8x4-packed emb
__device__ float g_normX[NTOK];
__device__ float g_normE[MC];
__device__ float g_sx[NTOK];              // per-row dequant scale
__device__ float g_se[MC];                // per-code dequant scale
__device__ int   g_cand[NTOK * NCAND];
__device__ float g_counts[MC];
__device__ float g_sumsq;

static __device__ __forceinline__ uint32_t s2u(const void* p) {
    uint32_t a;
    asm("{ .reg .u64 t; cvta.to.shared.u64 t, %1; cvt.u32.u64 %0, t; }" : "=r"(a) : "l"(p));
    return a;
}
static __device__ __forceinline__ float fmarn(float a, float b, float c) {
    float d;
    asm("fma.rn.f32 %0, %1, %2, %3;" : "=f"(d) : "f"(a), "f"(b), "f"(c));
    return d;
}
#define CP_ASYNC16(dst, src) \
    asm volatile("cp.async.cg.shared.global [%0], [%1], 16;" :: "r"(dst), "l"(src))
#define CP_COMMIT()  asm volatile("cp.async.commit_group;" ::: "memory")
#define CP_WAIT(n)   asm volatile("cp.async.wait_group %0;" :: "n"(n) : "memory")

#define LDSM_X4(r0, r1, r2, r3, addr) \
    asm volatile("ldmatrix.sync.aligned.m8n8.x4.shared.b16 {%0,%1,%2,%3}, [%4];" \
        : "=r"(r0), "=r"(r1), "=r"(r2), "=r"(r3) : "r"(addr))

static __device__ __forceinline__ void imma(int& c0, int& c1, int& c2, int& c3,
                                            uint32_t a0, uint32_t a1, uint32_t a2, uint32_t a3,
                                            uint32_t b0, uint32_t b1) {
    asm volatile(
        "mma.sync.aligned.m16n8k32.row.col.s32.s8.s8.s32 "
        "{%0,%1,%2,%3}, {%4,%5,%6,%7}, {%8,%9}, {%0,%1,%2,%3};"
        : "+r"(c0), "+r"(c1), "+r"(c2), "+r"(c3)
        : "r"(a0), "r"(a1), "r"(a2), "r"(a3), "r"(b0), "r"(b1));
}

// ---------------- s8 quantize + exact row norms (bitwise-R1 norm arithmetic) ----------------
// which==1 (embedding) also zeroes g_counts/g_sumsq from block 0 (init fused)
__global__ void convert_kernel(const float* __restrict__ src, int which) {
    if (which && blockIdx.x == 0) {
        for (int i = threadIdx.x; i < MC; i += 256) g_counts[i] = 0.0f;
        if (threadIdx.x == 0) g_sumsq = 0.0f;
    }
    int warp = threadIdx.x >> 5, lane = threadIdx.x & 31;
    int row = blockIdx.x * 8 + warp;
    uint32_t* dst = which ? g_eq : g_xq;
    const float4* r4 = (const float4*)(src + ((size_t)row << 8));
    float4 v0 = r4[lane], v1 = r4[lane + 32];

    // exact norm (same arithmetic order as all passing rounds)
    float s = 0.0f;
    s += v0.x * v0.x + v0.y * v0.y + v0.z * v0.z + v0.w * v0.w;
    s += v1.x * v1.x + v1.y * v1.y + v1.z * v1.z + v1.w * v1.w;
#pragma unroll
    for (int o = 16; o > 0; o >>= 1) s += __shfl_xor_sync(0xffffffffu, s, o);

    // row max-abs
    float m = fabsf(v0.x);
    m = fmaxf(m, fabsf(v0.y)); m = fmaxf(m, fabsf(v0.z)); m = fmaxf(m, fabsf(v0.w));
    m = fmaxf(m, fabsf(v1.x)); m = fmaxf(m, fabsf(v1.y));
    m = fmaxf(m, fabsf(v1.z)); m = fmaxf(m, fabsf(v1.w));
#pragma unroll
    for (int o = 16; o > 0; o >>= 1) m = fmaxf(m, __shfl_xor_sync(0xffffffffu, m, o));
    m = fmaxf(m, 1e-30f);
    float inv = 127.0f / m;

    uint32_t p0, p1;
    {
        int a = __float2int_rn(v0.x * inv), b = __float2int_rn(v0.y * inv);
        int c = __float2int_rn(v0.z * inv), d = __float2int_rn(v0.w * inv);
        p0 = (a & 255) | ((b & 255) << 8) | ((c & 255) << 16) | ((d & 255) << 24);
        a = __float2int_rn(v1.x * inv); b = __float2int_rn(v1.y * inv);
        c = __float2int_rn(v1.z * inv); d = __float2int_rn(v1.w * inv);
        p1 = (a & 255) | ((b & 255) << 8) | ((c & 255) << 16) | ((d & 255) << 24);
    }
    dst[(size_t)row * 64 + lane]      = p0;
    dst[(size_t)row * 64 + lane + 32] = p1;

    if (lane == 0) {
        if (which) { g_normE[row] = s; g_se[row] = m * (1.0f / 127.0f); }
        else       { g_normX[row] = s; g_sx[row] = m * (1.0f / 127.0f); }
    }
}

// ---------------- 16-warp S8 IMMA GEMM: resident A, 3-stage B, 1 barrier/chunk ----------------
// warp grid 2(M) x 8(N); warp tile 64x32; per-thread acc 4x4x4 (s32)
__global__ __launch_bounds__(512, 1)
void mma_argmin_kernel() {
    extern __shared__ char smem[];
    uint32_t sb = s2u(smem);
    float* sne = (float*)(smem + OFF_SNE);
    float* sse = (float*)(smem + OFF_SSE);
    float* sV1 = (float*)(smem + OFF_RED);          // [32][128]
    float* sV2 = sV1 + 4096;
    int*   sI1 = (int*)(sV2 + 4096);
    int*   sI2 = sI1 + 4096;

    int tid = threadIdx.x, wid = tid >> 5, lane = tid & 31;
    int warp_m = wid & 1, warp_n = wid >> 1;        // 2 x 8
    int lg = lane >> 2, lt = lane & 3;
    int row0 = blockIdx.x * BM;
    int slot = warp_n * 4 + lt;                     // 32 slots

    for (int i = tid; i < MC; i += 512) { sne[i] = g_normE[i]; sse[i] = g_se[i]; }
    for (int i = tid; i < 4096; i += 512) {
        sV1[i] = FINF; sV2[i] = FINF; sI1[i] = IMAX; sI2[i] = IMAX;
    }

    float nx8[8], sx8[8];
#pragma unroll
    for (int mt = 0; mt < 4; ++mt)
#pragma unroll
        for (int i = 0; i < 2; ++i) {
            int r = row0 + warp_m * 64 + mt * 16 + i * 8 + lg;
            nx8[mt * 2 + i] = g_normX[r];
            sx8[mt * 2 + i] = g_sx[r];
        }

    int acc[4][4][4];
#pragma unroll
    for (int mt = 0; mt < 4; ++mt)
#pragma unroll
        for (int n8 = 0; n8 < 4; ++n8)
#pragma unroll
            for (int q = 0; q < 4; ++q) acc[mt][n8][q] = 0;

    // ldmatrix per-lane base offsets
    int grp = lane >> 3, lr = lane & 7;
    uint32_t aOff[4];                               // into resident A (272B stride)
#pragma unroll
    for (int mt = 0; mt < 4; ++mt)
        aOff[mt] = (uint32_t)OFF_A
                 + (uint32_t)((warp_m * 64 + mt * 16 + lr + (grp & 1) * 8) * ALDPB)
                 + (uint32_t)((grp >> 1) * 16);
    uint32_t bOff = (uint32_t)((warp_n * 32 + grp * 8 + lr) * LDPB);

    // resident-A load: 2048 16B segs / 512 thr = 4 contiguous per thread
    {
        int a_r = tid >> 2, a_s = (tid & 3) * 4;    // row (4 thr/row), first seg
        const char* asrc = (const char*)g_xq + ((size_t)(row0 + a_r) << 8) + a_s * 16;
        uint32_t adst = sb + OFF_A + a_r * ALDPB + a_s * 16;
#pragma unroll
        for (int j = 0; j < 4; ++j) CP_ASYNC16(adst + j * 16, asrc + j * 16);
        CP_COMMIT();
    }

    // B loader: 128 bytes of K per row per chunk, 3-stage ring
    int b_r = tid >> 1, b_s = (tid & 1) * 4;        // B row (2 thr/row), first seg
    auto load_chunk = [&](int c) {
        int nt = c >> 1, kc = c & 1;
        int kbyte = kc * 128;
        uint32_t stage = sb + OFF_STAGE + (c % 3) * B_BYTES;
        const char* bsrc = (const char*)g_eq + ((size_t)(nt * BN + b_r) << 8) + kbyte + b_s * 16;
        uint32_t bdst = stage + b_r * LDPB + b_s * 16;
#pragma unroll
        for (int j = 0; j < 4; ++j) CP_ASYNC16(bdst + j * 16, bsrc + j * 16);
        CP_COMMIT();
    };

    load_chunk(0);
    load_chunk(1);

    for (int c = 0; c < NCHUNKS; ++c) {
        if (c + 2 < NCHUNKS) CP_WAIT(1); else CP_WAIT(0);
        __syncthreads();   // chunk c visible everywhere; chunk c-1 compute done by all
        if (c + 2 < NCHUNKS) load_chunk(c + 2);

        uint32_t stageAddr = sb + OFF_STAGE + (c % 3) * B_BYTES;
        uint32_t aK = (uint32_t)((c & 1) * 128);

#pragma unroll
        for (int ks = 0; ks < 4; ++ks) {            // 4 x k32 per chunk
            uint32_t kb = ks * 32;                  // 32 s8 = 32 bytes
            uint32_t a[4][4], b0[4], b1[4];
#pragma unroll
            for (int mt = 0; mt < 4; ++mt)
                LDSM_X4(a[mt][0], a[mt][1], a[mt][2], a[mt][3],
                        sb + aOff[mt] + aK + kb);
            LDSM_X4(b0[0], b0[1], b0[2], b0[3], stageAddr + bOff + kb);
            LDSM_X4(b1[0], b1[1], b1[2], b1[3], stageAddr + bOff + kb + 16);
#pragma unroll
            for (int mt = 0; mt < 4; ++mt)
#pragma unroll
                for (int n8 = 0; n8 < 4; ++n8)
                    imma(acc[mt][n8][0], acc[mt][n8][1], acc[mt][n8][2], acc[mt][n8][3],
                         a[mt][0], a[mt][1], a[mt][2], a[mt][3], b0[n8], b1[n8]);
        }

        if ((c & 1) == 1) {
            int nt = c >> 1;
#pragma unroll
            for (int mt = 0; mt < 4; ++mt)
#pragma unroll
                for (int i = 0; i < 2; ++i) {
                    int rl = warp_m * 64 + mt * 16 + i * 8 + lg;
                    float nx = nx8[mt * 2 + i];
                    float sx = sx8[mt * 2 + i];
                    float tv1 = FINF, tv2 = FINF; int ti1 = IMAX, ti2 = IMAX;
#pragma unroll
                    for (int n8 = 0; n8 < 4; ++n8) {
                        int cbase = nt * BN + warp_n * 32 + n8 * 8 + 2 * lt;
#pragma unroll
                        for (int q = 0; q < 2; ++q) {
                            float dot = (float)acc[mt][n8][i * 2 + q] * (sx * sse[cbase + q]);
                            float d = (sne[cbase + q] + nx) - 2.0f * dot;
                            int cc = cbase + q;
                            if (d < tv1 || (d == tv1 && cc < ti1)) {
                                tv2 = tv1; ti2 = ti1; tv1 = d; ti1 = cc;
                            } else if (d < tv2 || (d == tv2 && cc < ti2)) {
                                tv2 = d; ti2 = cc;
                            }
                        }
                    }
                    int o = slot * 128 + rl;
                    float mv1 = sV1[o], mv2 = sV2[o]; int mi1 = sI1[o], mi2 = sI2[o];
                    if (tv1 < mv1 || (tv1 == mv1 && ti1 < mi1)) {
                        mv2 = mv1; mi2 = mi1; mv1 = tv1; mi1 = ti1;
                    } else if (tv1 < mv2 || (tv1 == mv2 && ti1 < mi2)) {
                        mv2 = tv1; mi2 = ti1;
                    }
                    if (tv2 < mv1 || (tv2 == mv1 && ti2 < mi1)) {
                        mv2 = mv1; mi2 = mi1; mv1 = tv2; mi1 = ti2;
                    } else if (tv2 < mv2 || (tv2 == mv2 && ti2 < mi2)) {
                        mv2 = tv2; mi2 = ti2;
                    }
                    sV1[o] = mv1; sV2[o] = mv2; sI1[o] = mi1; sI2[o] = mi2;
                }
#pragma unroll
            for (int mt = 0; mt < 4; ++mt)
#pragma unroll
                for (int n8 = 0; n8 < 4; ++n8)
#pragma unroll
                    for (int q = 0; q < 4; ++q) acc[mt][n8][q] = 0;
        }
    }
    __syncthreads();   // sketch complete before selection

    // per-row top-NCAND of 32 slots x best-2 = 64 candidates
    if (tid < BM) {
        unsigned usedA = 0, usedB = 0;
#pragma unroll 1
        for (int sel = 0; sel < NCAND; ++sel) {
            float bv = FINF; int bi = IMAX; int bs = 0; int barr = 0;
            for (int s = 0; s < 32; ++s) {
                float v1 = sV1[s * 128 + tid]; int i1 = sI1[s * 128 + tid];
                float v2 = sV2[s * 128 + tid]; int i2 = sI2[s * 128 + tid];
                bool okA = !((usedA >> s) & 1u), okB = !((usedB >> s) & 1u);
                if (okA && (v1 < bv || (v1 == bv && i1 < bi))) { bv = v1; bi = i1; bs = s; barr = 0; }
                if (okB && (v2 < bv || (v2 == bv && i2 < bi))) { bv = v2; bi = i2; bs = s; barr = 1; }
            }
            if (barr) usedB |= 1u << bs; else usedA |= 1u << bs;
            g_cand[(size_t)(row0 + tid) * NCAND + sel] = bi;
        }
    }
}

// ---------------- fused refine (SERIAL-chain exact fp32) + gather + loss + histogram ----------------
__global__ __launch_bounds__(128, 8)
void refine_gather_kernel(const float* __restrict__ x, const float* __restrict__ emb,
                          float* __restrict__ d_out, long long idx_off, int write_idx) {
    __shared__ float sx[4][D];            // x rows
    __shared__ float se[4][NCAND * ELD];  // candidate rows, stride ELD
    int warp = threadIdx.x >> 5, lane = threadIdx.x & 31;
    int row = blockIdx.x * 4 + warp;

    int ci = 0;
    if (lane < NCAND) ci = g_cand[(size_t)row * NCAND + lane];
    int cj[NCAND];
#pragma unroll
    for (int j = 0; j < NCAND; ++j) cj[j] = __shfl_sync(0xffffffffu, ci, j);

    const float4* x4 = (const float4*)(x + ((size_t)row << 8));
    float4 xv0 = x4[lane], xv1 = x4[lane + 32];
    *(float4*)&sx[warp][lane * 4]        = xv0;
    *(float4*)&sx[warp][128 + lane * 4]  = xv1;

#pragma unroll
    for (int j = 0; j < NCAND; ++j) {
        const float4* e4 = (const float4*)(emb + ((size_t)cj[j] << 8));
        *(float4*)&se[warp][j * ELD + lane * 4]       = __ldg(&e4[lane]);
        *(float4*)&se[warp][j * ELD + 128 + lane * 4] = __ldg(&e4[lane + 32]);
    }
    __syncwarp();

    float myd = FINF;
    if (lane < NCAND) {
        const float* xs = sx[warp];
        const float* es = &se[warp][lane * ELD];
        float dot = 0.0f;
#pragma unroll 8
        for (int k4 = 0; k4 < 64; ++k4) {
            float4 xv = *(const float4*)&xs[k4 * 4];
            float4 ev = *(const float4*)&es[k4 * 4];
            dot = fmarn(xv.x, ev.x, dot);
            dot = fmarn(xv.y, ev.y, dot);
            dot = fmarn(xv.z, ev.z, dot);
            dot = fmarn(xv.w, ev.w, dot);
        }
        myd = (g_normX[row] + g_normE[cj[lane]]) - 2.0f * dot;
    }
    float dv[NCAND];
#pragma unroll
    for (int j = 0; j < NCAND; ++j) dv[j] = __shfl_sync(0xffffffffu, myd, j);
    float bv = FINF; int bi = IMAX; int bj = 0;
#pragma unroll
    for (int j = 0; j < NCAND; ++j) {
        if (dv[j] < bv || (dv[j] == bv && cj[j] < bi)) { bv = dv[j]; bi = cj[j]; bj = j; }
    }
    if (lane == 0 && write_idx) d_out[idx_off + row] = (float)bi;

    const float* qs = &se[warp][bj * ELD];
    float4* o4 = (float4*)(d_out + ((size_t)row << 8));
    float s = 0.0f;
    {
        float4 q = *(const float4*)&qs[lane * 4];
        float4 o;
        o.x = xv0.x + (q.x - xv0.x); o.y = xv0.y + (q.y - xv0.y);
        o.z = xv0.z + (q.z - xv0.z); o.w = xv0.w + (q.w - xv0.w);
        o4[lane] = o;
        float dx = xv0.x - q.x, dy = xv0.y - q.y, dz = xv0.z - q.z, dw = xv0.w - q.w;
        s += dx * dx + dy * dy + dz * dz + dw * dw;
    }
    {
        float4 q = *(const float4*)&qs[128 + lane * 4];
        float4 o;
        o.x = xv1.x + (q.x - xv1.x); o.y = xv1.y + (q.y - xv1.y);
        o.z = xv1.z + (q.z - xv1.z); o.w = xv1.w + (q.w - xv1.w);
        o4[lane + 32] = o;
        float dx = xv1.x - q.x, dy = xv1.y - q.y, dz = xv1.z - q.z, dw = xv1.w - q.w;
        s += dx * dx + dy * dy + dz * dz + dw * dw;
    }
#pragma unroll
    for (int o = 16; o > 0; o >>= 1) s += __shfl_xor_sync(0xffffffffu, s, o);
    if (lane == 0) {
        atomicAdd(&g_sumsq, s);
        atomicAdd(&g_counts[bi], 1.0f);
    }
}

// ---------------- loss + perplexity ----------------
__global__ void finalize_kernel(float* __restrict__ d_out, long long loss_off,
                                long long perp_off) {
    __shared__ float red[1024];
    int t = threadIdx.x;
    float p = g_counts[t] * (1.0f / (float)NTOK);
    red[t] = p * logf(p + 1e-10f);
    __syncthreads();
    for (int s = 512; s > 0; s >>= 1) {
        if (t < s) red[t] += red[t + s];
        __syncthreads();
    }
    if (t == 0) {
        d_out[loss_off] = 0.25f * g_sumsq / ((float)NTOK * (float)D);
        d_out[perp_off] = expf(-red[0]);
    }
}

// ---------------- launch ----------------
extern "C" void kernel_launch(void* const* d_in, const int* in_sizes, int n_in,
                              void* d_out, int out_size) {
    const float* x   = (const float*)d_in[0];
    const float* emb = (const float*)d_in[1];
    float* out = (float*)d_out;

    int NT = in_sizes[0] / D;
    long long qn = (long long)in_sizes[0];
    long long loss_off = qn;
    long long idx_off  = qn + 1;
    long long perp_off = qn + 1 + NT;
    int full = (out_size >= (int)(qn + NT + 2)) ? 1 : 0;

    cudaFuncSetAttribute(mma_argmin_kernel, cudaFuncAttributeMaxDynamicSharedMemorySize,
                         SMEM_TOTAL);

    convert_kernel<<<NT / 8, 256>>>(x, 0);
    convert_kernel<<<MC / 8, 256>>>(emb, 1);
    mma_argmin_kernel<<<NT / BM, 512, SMEM_TOTAL>>>();
    refine_gather_kernel<<<NT / 4, 128>>>(x, emb, out, idx_off, full);
    if (full) finalize_kernel<<<1, 1024>>>(out, loss_off, perp_off);
}